// round 3
// baseline (speedup 1.0000x reference)
#include <cuda_runtime.h>
#include <cuda_bf16.h>
#include <math.h>

#define N_NODES 50000
#define N_EDGES 800000
#define FEAT    128
#define HEADS   8
#define CH      16

// ---------------- scratch (no allocs; referenced ONLY from device code) ----------
static __device__ __align__(16) float g_bufA[(size_t)N_NODES * FEAT];
static __device__ __align__(16) float g_bufB[(size_t)N_NODES * FEAT];
static __device__ float g_alsrc[N_NODES * HEADS];
static __device__ float g_aldst[N_NODES * HEADS];
static __device__ int   g_src[N_EDGES];
static __device__ int   g_dst[N_EDGES];
static __device__ int   g_rowptr[N_NODES + 1];
static __device__ int   g_cnt[N_NODES];
static __device__ int   g_fill[N_NODES];
static __device__ int   g_col[N_EDGES];
static __device__ int   g_incl[N_NODES];
static __device__ int   g_bsum[64];
static __device__ float g_gsum[16];
static __device__ int   g_is64;

__device__ __forceinline__ float lrelu02(float x) { return x > 0.f ? x : 0.2f * x; }
__device__ __forceinline__ float elu1(float x)    { return x > 0.f ? x : (__expf(x) - 1.f); }
__device__ __forceinline__ int   clampN(int v)    { return v < 0 ? 0 : (v >= N_NODES ? N_NODES - 1 : v); }

// ---------------- edge dtype probe + decode ----------------
// If edge_index is int64 (values < 2^31, nonneg), every odd 32-bit word is 0.
// If int32, odd words are node ids — OR over 1024 of them is nonzero w.p. ~1.
__global__ void k_detect(const unsigned int* __restrict__ w) {
    __shared__ unsigned int sh[1024];
    int t = threadIdx.x;
    sh[t] = w[2 * t + 1];
    __syncthreads();
    for (int off = 512; off > 0; off >>= 1) {
        if (t < off) sh[t] |= sh[t + off];
        __syncthreads();
    }
    if (t == 0) g_is64 = (sh[0] == 0u) ? 1 : 0;
}

__global__ void k_decode(const void* __restrict__ eiv) {
    int e = blockIdx.x * blockDim.x + threadIdx.x;
    if (e >= N_EDGES) return;
    int s, d;
    if (g_is64) {
        const long long* p = (const long long*)eiv;
        s = (int)p[e];
        d = (int)p[N_EDGES + e];
    } else {
        const int* p = (const int*)eiv;
        s = p[e];
        d = p[N_EDGES + e];
    }
    g_src[e] = clampN(s);
    g_dst[e] = clampN(d);
}

// ---------------- CSR build ----------------
__global__ void k_zero() {
    int i = blockIdx.x * blockDim.x + threadIdx.x;
    if (i < N_NODES) { g_cnt[i] = 0; g_fill[i] = 0; }
    if (i < 16) g_gsum[i] = 0.f;
}

__global__ void k_count() {
    int e = blockIdx.x * blockDim.x + threadIdx.x;
    if (e >= N_EDGES) return;
    atomicAdd(&g_cnt[g_dst[e]], 1);
}

__global__ void k_scan1() {
    __shared__ int sh[1024];
    int t = threadIdx.x;
    int g = blockIdx.x * 1024 + t;
    int v = (g < N_NODES) ? g_cnt[g] : 0;
    sh[t] = v;
    __syncthreads();
    for (int off = 1; off < 1024; off <<= 1) {
        int add = (t >= off) ? sh[t - off] : 0;
        __syncthreads();
        sh[t] += add;
        __syncthreads();
    }
    if (g < N_NODES) g_incl[g] = sh[t];
    if (t == 1023) g_bsum[blockIdx.x] = sh[1023];
}

__global__ void k_scan2(int nchunks) {
    if (threadIdx.x == 0) {
        int acc = 0;
        for (int i = 0; i < nchunks; i++) { int v = g_bsum[i]; g_bsum[i] = acc; acc += v; }
    }
}

__global__ void k_scan3() {
    int i = blockIdx.x * blockDim.x + threadIdx.x;
    if (i >= N_NODES) return;
    g_rowptr[i + 1] = g_incl[i] + g_bsum[i >> 10];
    if (i == 0) g_rowptr[0] = 0;
}

__global__ void k_scatter() {
    int e = blockIdx.x * blockDim.x + threadIdx.x;
    if (e >= N_EDGES) return;
    int d = g_dst[e];
    int pos = g_rowptr[d] + atomicAdd(&g_fill[d], 1);
    g_col[pos] = g_src[e];
}

// ---------------- SGEMM: g_bufA[M,128] = A[M,K] @ W[K,128] ----------------
// SRC = 0: A = Ain (harness input x);  SRC = 1: A = g_bufB
template <int SRC>
__global__ void k_gemm(const float* __restrict__ Ain, const float* __restrict__ W,
                       int M, int K) {
    const float* __restrict__ A = (SRC == 0) ? Ain : (const float*)g_bufB;
    float* __restrict__ C = g_bufA;

    __shared__ __align__(16) float As[16][65];
    __shared__ __align__(16) float Ws[16][128];
    const int tid = threadIdx.x;
    const int tr  = tid >> 5;
    const int tc  = tid & 31;
    const int row0 = blockIdx.x * 64;

    float acc[8][4];
#pragma unroll
    for (int i = 0; i < 8; i++)
#pragma unroll
        for (int j = 0; j < 4; j++) acc[i][j] = 0.f;

    const int la_row = tid >> 2;
    const int la_k   = (tid & 3) * 4;

    for (int k0 = 0; k0 < K; k0 += 16) {
        int ar = row0 + la_row;
        float4 av = make_float4(0.f, 0.f, 0.f, 0.f);
        if (ar < M) av = *(const float4*)&A[(size_t)ar * K + k0 + la_k];
        As[la_k + 0][la_row] = av.x;
        As[la_k + 1][la_row] = av.y;
        As[la_k + 2][la_row] = av.z;
        As[la_k + 3][la_row] = av.w;
#pragma unroll
        for (int i = 0; i < 2; i++) {
            int f = tid + i * 256;
            int wr = f >> 5;
            int wc = (f & 31) * 4;
            *(float4*)&Ws[wr][wc] = *(const float4*)&W[(size_t)(k0 + wr) * 128 + wc];
        }
        __syncthreads();
#pragma unroll
        for (int kk = 0; kk < 16; kk++) {
            float a[8];
#pragma unroll
            for (int i = 0; i < 8; i++) a[i] = As[kk][tr * 8 + i];
            float4 b = *(const float4*)&Ws[kk][tc * 4];
#pragma unroll
            for (int i = 0; i < 8; i++) {
                acc[i][0] += a[i] * b.x;
                acc[i][1] += a[i] * b.y;
                acc[i][2] += a[i] * b.z;
                acc[i][3] += a[i] * b.w;
            }
        }
        __syncthreads();
    }
#pragma unroll
    for (int i = 0; i < 8; i++) {
        int r = row0 + tr * 8 + i;
        if (r < M) {
            float4 v = make_float4(acc[i][0], acc[i][1], acc[i][2], acc[i][3]);
            *(float4*)&C[(size_t)r * 128 + tc * 4] = v;
        }
    }
}

// ---------------- attention logit projections (h = g_bufA) ----------------
__global__ void k_al(const float* __restrict__ a_src, const float* __restrict__ a_dst) {
    int t = blockIdx.x * blockDim.x + threadIdx.x;
    if (t >= N_NODES * HEADS) return;
    int n = t >> 3, j = t & 7;
    const float* hp = g_bufA + (size_t)n * FEAT + j * CH;
    const float* as = a_src + j * CH;
    const float* ad = a_dst + j * CH;
    float ss = 0.f, ds = 0.f;
#pragma unroll
    for (int c = 0; c < CH; c++) { float v = hp[c]; ss += v * as[c]; ds += v * ad[c]; }
    g_alsrc[t] = ss;
    g_aldst[t] = ds;
}

// ---------------- per-node softmax + aggregation (one warp / node), h = g_bufA ----
// MODE 0: g_bufB[n*128+k] = elu(agg + bias[k])        (layers 1,2)
// MODE 1: outp[n*16+c]    = mean_heads(agg) + bias[c] (layer 3 -> d_out)
template <int MODE>
__global__ void k_agg(const float* __restrict__ bias, float* __restrict__ outp) {
    int gw = (blockIdx.x * blockDim.x + threadIdx.x) >> 5;
    if (gw >= N_NODES) return;
    int lane = threadIdx.x & 31;
    int d = gw;
    const float* __restrict__ h = g_bufA;
    float* __restrict__ out = (MODE == 0) ? (float*)g_bufB : outp;
    int beg = g_rowptr[d], end = g_rowptr[d + 1];

    float adst = 0.f, asrc_self = 0.f;
    if (lane < 8) {
        adst      = g_aldst[d * 8 + lane];
        asrc_self = g_alsrc[d * 8 + lane];
    }
    // pass 1: per-head max over incoming edges + self loop
    float m = 0.f;
    if (lane < 8) {
        m = lrelu02(asrc_self + adst);
        for (int i = beg; i < end; i++) {
            int s = g_col[i];
            m = fmaxf(m, lrelu02(g_alsrc[s * 8 + lane] + adst));
        }
    }
    // pass 2: denominator + weighted accumulation
    const int head = lane >> 2;  // lane l owns channels 4l..4l+3 -> head l/4
    float den = 0.f;
    float4 acc = make_float4(0.f, 0.f, 0.f, 0.f);
    {   // self loop
        float p = 0.f;
        if (lane < 8) { p = __expf(lrelu02(asrc_self + adst) - m); den += p; }
        float w = __shfl_sync(0xffffffffu, p, head);
        float4 hv = *(const float4*)&h[(size_t)d * FEAT + lane * 4];
        acc.x += hv.x * w; acc.y += hv.y * w; acc.z += hv.z * w; acc.w += hv.w * w;
    }
    for (int i = beg; i < end; i++) {
        int s = g_col[i];
        float p = 0.f;
        if (lane < 8) { p = __expf(lrelu02(g_alsrc[s * 8 + lane] + adst) - m); den += p; }
        float w = __shfl_sync(0xffffffffu, p, head);
        float4 hv = *(const float4*)&h[(size_t)s * FEAT + lane * 4];
        acc.x += hv.x * w; acc.y += hv.y * w; acc.z += hv.z * w; acc.w += hv.w * w;
    }
    float denw = __shfl_sync(0xffffffffu, den, head);
    float inv = 1.f / denw;
    acc.x *= inv; acc.y *= inv; acc.z *= inv; acc.w *= inv;

    if (MODE == 0) {
        float4 bb = *(const float4*)&bias[lane * 4];
        acc.x = elu1(acc.x + bb.x);
        acc.y = elu1(acc.y + bb.y);
        acc.z = elu1(acc.z + bb.z);
        acc.w = elu1(acc.w + bb.w);
        *(float4*)&out[(size_t)d * FEAT + lane * 4] = acc;
    } else {
#pragma unroll
        for (int off = 4; off <= 16; off <<= 1) {
            acc.x += __shfl_xor_sync(0xffffffffu, acc.x, off);
            acc.y += __shfl_xor_sync(0xffffffffu, acc.y, off);
            acc.z += __shfl_xor_sync(0xffffffffu, acc.z, off);
            acc.w += __shfl_xor_sync(0xffffffffu, acc.w, off);
        }
        if (lane < 4) {
            float4 bb = *(const float4*)&bias[lane * 4];
            float4 r;
            r.x = acc.x * 0.125f + bb.x;
            r.y = acc.y * 0.125f + bb.y;
            r.z = acc.z * 0.125f + bb.z;
            r.w = acc.w * 0.125f + bb.w;
            *(float4*)&out[(size_t)d * CH + lane * 4] = r;
        }
    }
}

// ---------------- anomaly head: 16 -> 32 relu -> 1 sigmoid ----------------
__global__ void k_anomaly(const float* __restrict__ w1, const float* __restrict__ b1,
                          const float* __restrict__ w2, const float* __restrict__ b2,
                          float* __restrict__ out) {
    int n = blockIdx.x * blockDim.x + threadIdx.x;
    if (n >= N_NODES) return;
    float hv[16];
#pragma unroll
    for (int c = 0; c < 16; c++) hv[c] = out[(size_t)n * 16 + c];
    float acc = b2[0];
#pragma unroll
    for (int u = 0; u < 32; u++) {
        float t = b1[u];
#pragma unroll
        for (int c = 0; c < 16; c++) t += hv[c] * w1[c * 32 + u];
        acc += fmaxf(t, 0.f) * w2[u];
    }
    out[800000 + n] = 1.f / (1.f + __expf(-acc));
}

// ---------------- graph mean (accumulate into g_gsum) ----------------
__global__ void k_gsum(const float* __restrict__ hout) {
    __shared__ float sh[256];
    int tid = threadIdx.x;
    float s = 0.f;
    size_t total = (size_t)N_NODES * 16;
    size_t stride = (size_t)gridDim.x * 256;
    for (size_t idx = (size_t)blockIdx.x * 256 + tid; idx < total; idx += stride)
        s += hout[idx];
    sh[tid] = s;
    __syncthreads();
    for (int off = 128; off >= 16; off >>= 1) {
        if (tid < off) sh[tid] += sh[tid + off];
        __syncthreads();
    }
    if (tid < 16) atomicAdd(&g_gsum[tid], sh[tid]);
}

// ---------------- graph classifier: 16 -> 64 relu -> 2 ----------------
__global__ void k_final(const float* __restrict__ w1, const float* __restrict__ b1,
                        const float* __restrict__ w2, const float* __restrict__ b2,
                        float* __restrict__ out) {
    __shared__ float emb[16];
    __shared__ float hid[64];
    int t = threadIdx.x;  // 64 threads
    if (t < 16) {
        float e = g_gsum[t] * (1.f / (float)N_NODES);
        emb[t] = e;
        out[850000 + t] = e;
    }
    __syncthreads();
    float s = b1[t];
#pragma unroll
    for (int c = 0; c < 16; c++) s += emb[c] * w1[c * 64 + t];
    hid[t] = fmaxf(s, 0.f);
    __syncthreads();
    if (t < 2) {
        float r = b2[t];
#pragma unroll
        for (int u = 0; u < 64; u++) r += hid[u] * w2[u * 2 + t];
        out[850016 + t] = r;
    }
}

// ---------------- launch ----------------
extern "C" void kernel_launch(void* const* d_in, const int* in_sizes, int n_in,
                              void* d_out, int out_size) {
    const float* x      = (const float*)d_in[0];
    const void*  ei     = d_in[1];
    const float* W1     = (const float*)d_in[2];
    const float* a1s    = (const float*)d_in[3];
    const float* a1d    = (const float*)d_in[4];
    const float* b1     = (const float*)d_in[5];
    const float* W2     = (const float*)d_in[6];
    const float* a2s    = (const float*)d_in[7];
    const float* a2d    = (const float*)d_in[8];
    const float* b2     = (const float*)d_in[9];
    const float* W3     = (const float*)d_in[10];
    const float* a3s    = (const float*)d_in[11];
    const float* a3d    = (const float*)d_in[12];
    const float* b3     = (const float*)d_in[13];
    const float* cls_w1 = (const float*)d_in[14];
    const float* cls_b1 = (const float*)d_in[15];
    const float* cls_w2 = (const float*)d_in[16];
    const float* cls_b2 = (const float*)d_in[17];
    const float* an_w1  = (const float*)d_in[18];
    const float* an_b1  = (const float*)d_in[19];
    const float* an_w2  = (const float*)d_in[20];
    const float* an_b2  = (const float*)d_in[21];
    float* out = (float*)d_out;

    const int TB = 256;
    const int nodeBlocks = (N_NODES + TB - 1) / TB;
    const int edgeBlocks = (N_EDGES + TB - 1) / TB;
    const int alBlocks   = (N_NODES * HEADS + TB - 1) / TB;
    const int aggBlocks  = (N_NODES * 32 + TB - 1) / TB;
    const int gemmBlocks = (N_NODES + 63) / 64;
    const int nchunks    = (N_NODES + 1023) / 1024;

    // decode edges (dtype-robust) + CSR by destination
    k_detect<<<1, 1024>>>((const unsigned int*)ei);
    k_decode<<<edgeBlocks, TB>>>(ei);
    k_zero<<<nodeBlocks, TB>>>();
    k_count<<<edgeBlocks, TB>>>();
    k_scan1<<<nchunks, 1024>>>();
    k_scan2<<<1, 32>>>(nchunks);
    k_scan3<<<nodeBlocks, TB>>>();
    k_scatter<<<edgeBlocks, TB>>>();

    // layer 1: 256 -> 8x16 concat, elu
    k_gemm<0><<<gemmBlocks, TB>>>(x, W1, N_NODES, 256);
    k_al<<<alBlocks, TB>>>(a1s, a1d);
    k_agg<0><<<aggBlocks, TB>>>(b1, nullptr);

    // layer 2: 128 -> 8x16 concat, elu
    k_gemm<1><<<gemmBlocks, TB>>>(nullptr, W2, N_NODES, 128);
    k_al<<<alBlocks, TB>>>(a2s, a2d);
    k_agg<0><<<aggBlocks, TB>>>(b2, nullptr);

    // layer 3: 128 -> 8x16 head-mean -> d_out h region
    k_gemm<1><<<gemmBlocks, TB>>>(nullptr, W3, N_NODES, 128);
    k_al<<<alBlocks, TB>>>(a3s, a3d);
    k_agg<1><<<aggBlocks, TB>>>(b3, out);

    // heads
    k_anomaly<<<nodeBlocks, TB>>>(an_w1, an_b1, an_w2, an_b2, out);
    k_gsum<<<64, TB>>>(out);
    k_final<<<1, 64>>>(cls_w1, cls_b1, cls_w2, cls_b2, out);
}